// round 6
// baseline (speedup 1.0000x reference)
#include <cuda_runtime.h>

// CrossAttention with seqlen-1 K/V broadcast:
//   out[b,t,:] = (visual_features[b] @ Wv + bv) @ Wp + bp   for every t.
// Softmax over T identical logits is exactly uniform; averaging T identical
// value rows returns the row. x/Wq/Wk are mathematically irrelevant.
//
// 2 graph nodes:
//   1) fused_kernel (grid 256 x 128 thr, internal grid barriers):
//        phase1: g_part[sp]  = partial(vf @ Wv)
//        phase2: z-slice reduce (+bv), g_part2[sp] = partial(z @ Wp)
//        phase3: g_w = bp + sum_sp g_part2
//   2) bcast: out[b,t,:] = g_w[b,:]   (grid 512 x 256 thr)

#define CC 1024
#define BB 4
#define TT_TOTAL 1024
#define SPLITK 32
#define KCH (CC / SPLITK)   // 32
#define GRID_FUSED 256

__device__ float g_part [SPLITK][BB * CC];
__device__ float g_part2[SPLITK][BB * CC];
__device__ float g_w[BB * CC];
__device__ unsigned g_ctr1;   // zero-init, monotonic across replays
__device__ unsigned g_ctr2;

// Grid-wide barrier, graph-replay safe: monotonic ticket counter, no reset.
__device__ __forceinline__ void grid_barrier(unsigned* ctr)
{
    __syncthreads();
    if (threadIdx.x == 0) {
        __threadfence();                       // release this block's stores
        unsigned old = atomicAdd(ctr, 1u);
        unsigned target = (old / GRID_FUSED + 1u) * GRID_FUSED;
        while (*(volatile unsigned*)ctr < target) { }
    }
    __syncthreads();
    __threadfence();                           // acquire other blocks' stores
}

__global__ void __launch_bounds__(128)
fused_kernel(const float* __restrict__ vf,    // [BB][CC]
             const float* __restrict__ Wv,    // [CC][CC]
             const float* __restrict__ bv,    // [CC]
             const float* __restrict__ Wp,    // [CC][CC]
             const float* __restrict__ bp)    // [CC]
{
    __shared__ float s_buf[BB][KCH];
    __shared__ float s_red[128];

    const int tid = threadIdx.x;              // 0..127
    const int jb  = blockIdx.x & 7;           // 0..7  (column block)
    const int sp  = blockIdx.x >> 3;          // 0..31 (K split)
    const int j   = jb * 128 + tid;
    const int k0  = sp * KCH;
    const int lb  = tid >> 5;                 // b for the 128<->(b,i) map
    const int li  = tid & 31;                 // i

    // ---- phase 1: g_part[sp][b*CC+j] = sum_{i in chunk} vf[b][i] * Wv[i][j]
    s_buf[lb][li] = vf[lb * CC + k0 + li];
    __syncthreads();
    {
        float a0 = 0.f, a1 = 0.f, a2 = 0.f, a3 = 0.f;
        const float* __restrict__ Wc = Wv + (size_t)k0 * CC + j;
        #pragma unroll
        for (int i = 0; i < KCH; i++) {
            float wv = Wc[(size_t)i * CC];
            a0 += s_buf[0][i] * wv;
            a1 += s_buf[1][i] * wv;
            a2 += s_buf[2][i] * wv;
            a3 += s_buf[3][i] * wv;
        }
        float* p = &g_part[sp][0];
        p[0 * CC + j] = a0;
        p[1 * CC + j] = a1;
        p[2 * CC + j] = a2;
        p[3 * CC + j] = a3;
    }

    grid_barrier(&g_ctr1);

    // ---- phase 2: reduce z slice (+bv), then g_part2[sp] = partial(z @ Wp)
    {
        float s = bv[k0 + li];
        #pragma unroll
        for (int sp2 = 0; sp2 < SPLITK; sp2++)
            s += g_part[sp2][lb * CC + k0 + li];
        s_buf[lb][li] = s;
    }
    __syncthreads();
    {
        float a0 = 0.f, a1 = 0.f, a2 = 0.f, a3 = 0.f;
        const float* __restrict__ Wc = Wp + (size_t)k0 * CC + j;
        #pragma unroll
        for (int i = 0; i < KCH; i++) {
            float wv = Wc[(size_t)i * CC];
            a0 += s_buf[0][i] * wv;
            a1 += s_buf[1][i] * wv;
            a2 += s_buf[2][i] * wv;
            a3 += s_buf[3][i] * wv;
        }
        float* p = &g_part2[sp][0];
        p[0 * CC + j] = a0;
        p[1 * CC + j] = a1;
        p[2 * CC + j] = a2;
        p[3 * CC + j] = a3;
    }

    grid_barrier(&g_ctr2);

    // ---- phase 3: g_w[e] = bp[e & 1023] + sum_sp g_part2[sp][e]
    // 256 blocks x 16 elements; 8 threads cooperate per element (4 sp each).
    {
        const int e   = blockIdx.x * 16 + (tid & 15);   // 0..4095
        const int spg = tid >> 4;                        // 0..7
        float s = 0.f;
        #pragma unroll
        for (int u = 0; u < 4; u++)
            s += g_part2[spg * 4 + u][e];
        s_red[tid] = s;
        __syncthreads();
        if (tid < 16) {
            int e0 = blockIdx.x * 16 + tid;
            float r = bp[e0 & (CC - 1)];
            #pragma unroll
            for (int g = 0; g < 8; g++)
                r += s_red[g * 16 + tid];
            g_w[e0] = r;
        }
    }
}

// ---------------------------------------------------------------------------
// bcast: out[b,t,:] = g_w[b,:].  512 blocks x 256 thr, 1 LDG.128 + 8 STG.128.
#define ROWS_PER_BLK 8
__global__ void __launch_bounds__(256)
bcast_kernel(float* __restrict__ out)         // [BB][T][CC]
{
    const int blocks_per_b = TT_TOTAL / ROWS_PER_BLK;   // 128
    const int b  = blockIdx.x >> 7;
    const int t0 = (blockIdx.x & (blocks_per_b - 1)) * ROWS_PER_BLK;

    const float4 wv = *(reinterpret_cast<const float4*>(&g_w[b * CC]) + threadIdx.x);

    float4* o = reinterpret_cast<float4*>(out + (size_t)(b * TT_TOTAL + t0) * CC)
                + threadIdx.x;
    #pragma unroll
    for (int t = 0; t < ROWS_PER_BLK; t++)
        o[(size_t)t * (CC / 4)] = wv;
}

extern "C" void kernel_launch(void* const* d_in, const int* in_sizes, int n_in,
                              void* d_out, int out_size)
{
    // metadata order: x, visual_features, Wq, bq, Wk, bk, Wv, bv, Wp, bp
    const float* vf = (const float*)d_in[1];
    const float* Wv = (const float*)d_in[6];
    const float* bv = (const float*)d_in[7];
    const float* Wp = (const float*)d_in[8];
    const float* bp = (const float*)d_in[9];
    float* out = (float*)d_out;

    fused_kernel<<<GRID_FUSED, 128>>>(vf, Wv, bv, Wp, bp);
    bcast_kernel<<<BB * (TT_TOTAL / ROWS_PER_BLK), 256>>>(out);
}